// round 2
// baseline (speedup 1.0000x reference)
#include <cuda_runtime.h>
#include <cstdint>

#define Bn 4
#define Tn 2048
#define Cn 1024
#define Hn 16
#define Dn 64
#define Mn (Bn * Tn)

// Scratch (static __device__ arrays: allowed, no runtime alloc)
__device__ float g_qkv[(size_t)Mn * 3 * Cn];   // [8192, 3072]
__device__ float g_att[(size_t)Mn * Cn];       // [8192, 1024]

// ---------------------------------------------------------------------------
// tf32 helpers
// ---------------------------------------------------------------------------
__device__ __forceinline__ uint32_t f32_to_tf32(float x) {
    uint32_t r;
    asm("cvt.rna.tf32.f32 %0, %1;" : "=r"(r) : "f"(x));
    return r;
}

__device__ __forceinline__ void split_tf32(float x, uint32_t& hi, uint32_t& lo) {
    hi = f32_to_tf32(x);
    float res = x - __uint_as_float(hi);
    lo = f32_to_tf32(res);
}

__device__ __forceinline__ void mma_tf32(float d[4], const uint32_t a[4], const uint32_t b[2]) {
    asm volatile(
        "mma.sync.aligned.m16n8k8.row.col.f32.tf32.tf32.f32 "
        "{%0,%1,%2,%3}, {%4,%5,%6,%7}, {%8,%9}, {%0,%1,%2,%3};"
        : "+f"(d[0]), "+f"(d[1]), "+f"(d[2]), "+f"(d[3])
        : "r"(a[0]), "r"(a[1]), "r"(a[2]), "r"(a[3]), "r"(b[0]), "r"(b[1]));
}

// ---------------------------------------------------------------------------
// GEMM + bias via 3xTF32 tensor-core mma:
//   C[M,N] = A[M,K] @ B[K,N] + bias[N]   (fp32-accurate)
// Block tile 128x128, BK=32, 256 threads = 8 warps in 2(M) x 4(N) grid,
// warp tile 64x32 = 4x4 mma tiles of m16n8k8.
// hi/lo tf32 split done ONCE at smem store (avoids per-fragment cvt storm).
// Smem strides (36 / 136) make mma fragment reads 32-bank conflict-free.
// ---------------------------------------------------------------------------
#define AS_STRIDE 36     // [m][k], m=128, k=32
#define BS_STRIDE 136    // [k][n], k=32, n=128
#define AS_ELEMS  (128 * AS_STRIDE)
#define BS_ELEMS  (32 * BS_STRIDE)
#define GEMM_SMEM_BYTES ((2 * AS_ELEMS + 2 * BS_ELEMS) * 4)

__global__ __launch_bounds__(256)
void gemm_tf32x3_bias(const float* __restrict__ A,
                      const float* __restrict__ Bm,
                      const float* __restrict__ bias,
                      float* __restrict__ Cm,
                      int M, int N, int K)
{
    extern __shared__ uint32_t smem[];
    uint32_t* As_hi = smem;
    uint32_t* As_lo = As_hi + AS_ELEMS;
    uint32_t* Bs_hi = As_lo + AS_ELEMS;
    uint32_t* Bs_lo = Bs_hi + BS_ELEMS;

    const int tid  = threadIdx.x;
    const int warp = tid >> 5;
    const int lane = tid & 31;
    const int wm   = warp >> 2;   // 0..1
    const int wn   = warp & 3;    // 0..3
    const int row0 = blockIdx.y * 128;
    const int col0 = blockIdx.x * 128;

    // global->smem assignment
    const int am = tid >> 1;           // 0..127
    const int ak = (tid & 1) * 16;     // 0 or 16
    const int bk = tid >> 3;           // 0..31
    const int bn = (tid & 7) * 16;     // 0..112

    const float* Ap = A  + (size_t)(row0 + am) * K + ak;
    const float* Bp = Bm + (size_t)bk * N + col0 + bn;

    float acc[4][4][4];
#pragma unroll
    for (int i = 0; i < 4; i++)
#pragma unroll
        for (int j = 0; j < 4; j++)
#pragma unroll
            for (int r = 0; r < 4; r++) acc[i][j][r] = 0.0f;

    // prefetch tile 0
    float4 apre[4], bpre[4];
#pragma unroll
    for (int i = 0; i < 4; i++) {
        apre[i] = *(const float4*)(Ap + i * 4);
        bpre[i] = *(const float4*)(Bp + i * 4);
    }

    const int NT = K / 32;
    const int ar = lane >> 2;    // 0..7
    const int ac = lane & 3;     // 0..3
    const int m0 = wm * 64;
    const int n0 = wn * 32;

    for (int kt = 0; kt < NT; kt++) {
        // split + store current tile
#pragma unroll
        for (int i = 0; i < 4; i++) {
            float av[4] = {apre[i].x, apre[i].y, apre[i].z, apre[i].w};
            float bv[4] = {bpre[i].x, bpre[i].y, bpre[i].z, bpre[i].w};
#pragma unroll
            for (int j = 0; j < 4; j++) {
                uint32_t hi, lo;
                split_tf32(av[j], hi, lo);
                int aidx = am * AS_STRIDE + ak + i * 4 + j;
                As_hi[aidx] = hi;
                As_lo[aidx] = lo;
                split_tf32(bv[j], hi, lo);
                int bidx = bk * BS_STRIDE + bn + i * 4 + j;
                Bs_hi[bidx] = hi;
                Bs_lo[bidx] = lo;
            }
        }
        __syncthreads();

        if (kt + 1 < NT) {   // prefetch next tile while computing
#pragma unroll
            for (int i = 0; i < 4; i++) {
                apre[i] = *(const float4*)(Ap + (kt + 1) * 32 + i * 4);
                bpre[i] = *(const float4*)(Bp + (size_t)(kt + 1) * 32 * N + i * 4);
            }
        }

#pragma unroll
        for (int ks = 0; ks < 4; ks++) {
            const int k0 = ks * 8;
            uint32_t a_hi[4][4], a_lo[4][4], b_hi[4][2], b_lo[4][2];
#pragma unroll
            for (int ni = 0; ni < 4; ni++) {
                int bb = (k0 + ac) * BS_STRIDE + n0 + ni * 8 + ar;
                b_hi[ni][0] = Bs_hi[bb];
                b_hi[ni][1] = Bs_hi[bb + 4 * BS_STRIDE];
                b_lo[ni][0] = Bs_lo[bb];
                b_lo[ni][1] = Bs_lo[bb + 4 * BS_STRIDE];
            }
#pragma unroll
            for (int mi = 0; mi < 4; mi++) {
                int ab = (m0 + mi * 16 + ar) * AS_STRIDE + k0 + ac;
                a_hi[mi][0] = As_hi[ab];
                a_hi[mi][1] = As_hi[ab + 8 * AS_STRIDE];
                a_hi[mi][2] = As_hi[ab + 4];
                a_hi[mi][3] = As_hi[ab + 8 * AS_STRIDE + 4];
                a_lo[mi][0] = As_lo[ab];
                a_lo[mi][1] = As_lo[ab + 8 * AS_STRIDE];
                a_lo[mi][2] = As_lo[ab + 4];
                a_lo[mi][3] = As_lo[ab + 8 * AS_STRIDE + 4];
            }
#pragma unroll
            for (int mi = 0; mi < 4; mi++)
#pragma unroll
                for (int ni = 0; ni < 4; ni++) {
                    mma_tf32(acc[mi][ni], a_hi[mi], b_hi[ni]);
                    mma_tf32(acc[mi][ni], a_hi[mi], b_lo[ni]);
                    mma_tf32(acc[mi][ni], a_lo[mi], b_hi[ni]);
                }
        }
        __syncthreads();
    }

    // epilogue: + bias, write fp32
#pragma unroll
    for (int mi = 0; mi < 4; mi++) {
        int r = row0 + m0 + mi * 16 + ar;
#pragma unroll
        for (int ni = 0; ni < 4; ni++) {
            int c = col0 + n0 + ni * 8 + ac * 2;
            float2 bv = *(const float2*)(&bias[c]);
            float2 o0, o1;
            o0.x = acc[mi][ni][0] + bv.x;
            o0.y = acc[mi][ni][1] + bv.y;
            o1.x = acc[mi][ni][2] + bv.x;
            o1.y = acc[mi][ni][3] + bv.y;
            *(float2*)(&Cm[(size_t)r * N + c])       = o0;
            *(float2*)(&Cm[(size_t)(r + 8) * N + c]) = o1;
        }
    }
}

// ---------------------------------------------------------------------------
// Flash attention, causal (unchanged fp32 version from round 1).
// ---------------------------------------------------------------------------
__global__ __launch_bounds__(128)
void attn_kernel(const float* __restrict__ qkv, float* __restrict__ att)
{
    __shared__ float Qs[64][64];
    __shared__ float KP[64][64];
    __shared__ float Vs[64][64];

    const int tid = threadIdx.x;
    const int tx  = tid & 15;
    const int ty  = tid >> 4;
    const int qt  = blockIdx.x;
    const int bh  = blockIdx.y;
    const int b   = bh >> 4;
    const int h   = bh & 15;
    const int q0  = qt * 64;

    const float* base = qkv + (size_t)b * Tn * (3 * Cn);

    {
        const int r  = tid >> 4;
        const int d0 = (tid & 15) * 4;
#pragma unroll
        for (int mm = 0; mm < 8; mm++) {
            int m = mm * 8 + r;
            float4 q4 = *(const float4*)(base + (size_t)(q0 + m) * (3 * Cn) + h * 64 + d0);
            int dd = d0 ^ ((m & 8) >> 1);
            *(float4*)(&Qs[m][dd]) = q4;
        }
    }

    float o[8][4];
    float mrow[8], lrow[8];
#pragma unroll
    for (int i = 0; i < 8; i++) {
        mrow[i] = -1e30f;
        lrow[i] = 0.0f;
#pragma unroll
        for (int j = 0; j < 4; j++) o[i][j] = 0.0f;
    }

    const float scale = 0.125f;
    const int m0 = ty * 8;
    const int n0 = tx * 4;
    const int qswz = ((m0 & 8) >> 1);

    for (int t = 0; t <= qt; t++) {
        const int kv0 = t * 64;
        __syncthreads();

        {
            const int r  = tid >> 4;
            const int d0 = (tid & 15) * 4;
#pragma unroll
            for (int mm = 0; mm < 8; mm++) {
                int n = mm * 8 + r;
                const float* kp = base + (size_t)(kv0 + n) * (3 * Cn) + Cn + h * 64 + d0;
                float4 k4 = *(const float4*)kp;
                KP[d0 + 0][n ^ (d0 + 0)] = k4.x;
                KP[d0 + 1][n ^ (d0 + 1)] = k4.y;
                KP[d0 + 2][n ^ (d0 + 2)] = k4.z;
                KP[d0 + 3][n ^ (d0 + 3)] = k4.w;
                float4 v4 = *(const float4*)(kp + Cn);
                *(float4*)(&Vs[n][d0]) = v4;
            }
        }
        __syncthreads();

        float s[8][4];
#pragma unroll
        for (int i = 0; i < 8; i++)
#pragma unroll
            for (int j = 0; j < 4; j++) s[i][j] = 0.0f;

#pragma unroll 4
        for (int d = 0; d < 64; d++) {
            float kb[4];
#pragma unroll
            for (int j = 0; j < 4; j++)
                kb[j] = KP[d][(n0 + j) ^ d];
#pragma unroll
            for (int i = 0; i < 8; i++) {
                float qa = Qs[m0 + i][d ^ qswz];
#pragma unroll
                for (int j = 0; j < 4; j++)
                    s[i][j] = fmaf(qa, kb[j], s[i][j]);
            }
        }

        if (t == qt) {
#pragma unroll
            for (int i = 0; i < 8; i++)
#pragma unroll
                for (int j = 0; j < 4; j++)
                    s[i][j] = (n0 + j > m0 + i) ? -1e30f : s[i][j] * scale;
        } else {
#pragma unroll
            for (int i = 0; i < 8; i++)
#pragma unroll
                for (int j = 0; j < 4; j++)
                    s[i][j] *= scale;
        }

#pragma unroll
        for (int i = 0; i < 8; i++) {
            float tm = fmaxf(fmaxf(s[i][0], s[i][1]), fmaxf(s[i][2], s[i][3]));
#pragma unroll
            for (int off = 8; off >= 1; off >>= 1)
                tm = fmaxf(tm, __shfl_xor_sync(0xffffffffu, tm, off));
            float mn   = fmaxf(mrow[i], tm);
            float corr = __expf(mrow[i] - mn);
            mrow[i] = mn;
            float rs = 0.0f;
#pragma unroll
            for (int j = 0; j < 4; j++) {
                float p = __expf(s[i][j] - mn);
                s[i][j] = p;
                rs += p;
            }
#pragma unroll
            for (int off = 8; off >= 1; off >>= 1)
                rs += __shfl_xor_sync(0xffffffffu, rs, off);
            lrow[i] = lrow[i] * corr + rs;
#pragma unroll
            for (int j = 0; j < 4; j++) o[i][j] *= corr;
        }

        __syncthreads();
#pragma unroll
        for (int i = 0; i < 8; i++)
            *(float4*)(&KP[m0 + i][n0]) = make_float4(s[i][0], s[i][1], s[i][2], s[i][3]);
        __syncthreads();

#pragma unroll 4
        for (int k = 0; k < 64; k++) {
            float4 vb = *(const float4*)(&Vs[k][n0]);
#pragma unroll
            for (int i = 0; i < 8; i++) {
                float pa = KP[m0 + i][k];
                o[i][0] = fmaf(pa, vb.x, o[i][0]);
                o[i][1] = fmaf(pa, vb.y, o[i][1]);
                o[i][2] = fmaf(pa, vb.z, o[i][2]);
                o[i][3] = fmaf(pa, vb.w, o[i][3]);
            }
        }
    }

#pragma unroll
    for (int i = 0; i < 8; i++) {
        float inv = 1.0f / lrow[i];
        int r = q0 + m0 + i;
        float4 ov = make_float4(o[i][0] * inv, o[i][1] * inv, o[i][2] * inv, o[i][3] * inv);
        *(float4*)(&att[((size_t)b * Tn + r) * Cn + h * 64 + n0]) = ov;
    }
}

// ---------------------------------------------------------------------------
extern "C" void kernel_launch(void* const* d_in, const int* in_sizes, int n_in,
                              void* d_out, int out_size)
{
    const float* x     = (const float*)d_in[0];  // [4,2048,1024]
    const float* Wqkv  = (const float*)d_in[1];  // [1024,3072]
    const float* bqkv  = (const float*)d_in[2];  // [3072]
    const float* Wproj = (const float*)d_in[3];  // [1024,1024]
    const float* bproj = (const float*)d_in[4];  // [1024]
    float* out = (float*)d_out;                  // [4,2048,1024]

    float *qkv_p = nullptr, *att_p = nullptr;
    cudaGetSymbolAddress((void**)&qkv_p, g_qkv);
    cudaGetSymbolAddress((void**)&att_p, g_att);

    cudaFuncSetAttribute(gemm_tf32x3_bias,
                         cudaFuncAttributeMaxDynamicSharedMemorySize,
                         GEMM_SMEM_BYTES);

    // 1) QKV = X @ W_qkv + b_qkv   (tensor cores, 3xTF32)
    gemm_tf32x3_bias<<<dim3((3 * Cn) / 128, Mn / 128), 256, GEMM_SMEM_BYTES>>>(
        x, Wqkv, bqkv, qkv_p, Mn, 3 * Cn, Cn);

    // 2) causal flash attention per (head, q-tile)
    attn_kernel<<<dim3(Tn / 64, Bn * Hn), 128>>>(qkv_p, att_p);

    // 3) out = att @ W_proj + b_proj  (tensor cores, 3xTF32)
    gemm_tf32x3_bias<<<dim3(Cn / 128, Mn / 128), 256, GEMM_SMEM_BYTES>>>(
        att_p, Wproj, bproj, out, Mn, Cn, Cn);
}